// round 11
// baseline (speedup 1.0000x reference)
#include <cuda_runtime.h>
#include <cuda_fp16.h>

// int4-quantized GEMV, QB=128, K=8192. fp16 tensors arrive upcast to fp32.
//   d_in[0] x       : float[8192]
//   d_in[1] packed_w: int32[N, 4096]  (each int32 holds ONE byte: lo nibble ->
//                     even k, hi nibble -> odd k, offset-8)
//   d_in[2] scales  : float[N, 64]
//   d_out  out      : float[N]
//
// R9 = R7 resubmission (R8/R9 infra flake, kernel never ran).
// Instruction-diet version (kernel was issue-limited, not DRAM-limited):
//  - two packed ints fused per unpack: v = b0|(b1<<16); one LOP3 per
//    ((v&0x000F000F)|0x64006400) and the >>4 variant; HSUB2 exact -> w-8.
//  - x deinterleaved into fp32 even/odd SMEM arrays: no x-side cvt.
//  - packed fma.rn.f32x2 (sm_100+) for dot and scale FMAs.
//  - static grid, 2 rows/warp, 8 rows/CTA (128 thr), grid=N/8, __ldcs weights.

#define FAST_K 8192

__device__ __forceinline__ float2 ffma2(float2 a, float2 b, float2 c) {
    unsigned long long ra = *reinterpret_cast<unsigned long long*>(&a);
    unsigned long long rb = *reinterpret_cast<unsigned long long*>(&b);
    unsigned long long rc = *reinterpret_cast<unsigned long long*>(&c);
    unsigned long long rr;
    asm("fma.rn.f32x2 %0, %1, %2, %3;" : "=l"(rr) : "l"(ra), "l"(rb), "l"(rc));
    return *reinterpret_cast<float2*>(&rr);
}

// Unpack 2 packed ints (4 weights) and accumulate into p (packed fp32x2).
//   b0 covers k, k+1 ; b1 covers k+2, k+3.
//   xe = {x[k], x[k+2]} ; xo = {x[k+1], x[k+3]}  (fp32)
__device__ __forceinline__ float2 dot4(unsigned b0, unsigned b1,
                                       float2 xe, float2 xo,
                                       __half2 off, float2 p)
{
    const unsigned v  = b0 | (b1 << 16);
    unsigned lo = (v & 0x000F000Fu) | 0x64006400u;          // one LOP3
    unsigned hi = ((v >> 4) & 0x000F000Fu) | 0x64006400u;   // SHF + LOP3
    __half2 wlo = __hsub2(*reinterpret_cast<__half2*>(&lo), off); // {w[k],w[k+2]}
    __half2 whi = __hsub2(*reinterpret_cast<__half2*>(&hi), off); // {w[k+1],w[k+3]}
    float2 flo = __half22float2(wlo);
    float2 fhi = __half22float2(whi);
    p = ffma2(flo, xe, p);
    p = ffma2(fhi, xo, p);
    return p;
}

__global__ void __launch_bounds__(128, 6)
q4gemv_fast3(const float* __restrict__ x,
             const int*   __restrict__ pw,
             const float* __restrict__ scales,
             float*       __restrict__ out,
             int N)
{
    __shared__ float xeven[FAST_K / 2];   // 16 KB: x[0],x[2],x[4],...
    __shared__ float xodd [FAST_K / 2];   // 16 KB: x[1],x[3],...
    __shared__ float scsm[8 * 64];        //  2 KB: 8 rows x 64 block scales

    const int tid  = threadIdx.x;
    const int base = blockIdx.x * 8;

    // Deinterleave x (fp32) into even/odd SMEM arrays.
    {
        const float4* xsrc = reinterpret_cast<const float4*>(x);
        float2* xe2 = reinterpret_cast<float2*>(xeven);
        float2* xo2 = reinterpret_cast<float2*>(xodd);
        #pragma unroll
        for (int i = 0; i < (FAST_K / 4) / 128; ++i) {      // 16 iters
            const int idx = tid + i * 128;
            float4 v = xsrc[idx];
            xe2[idx] = make_float2(v.x, v.z);
            xo2[idx] = make_float2(v.y, v.w);
        }
    }
    // Stage this block's 8x64 scales.
    {
        #pragma unroll
        for (int i = 0; i < 4; ++i) {
            const int idx = tid + i * 128;                  // 0..511
            scsm[idx] = scales[(size_t)(base + (idx >> 6)) * 64 + (idx & 63)];
        }
    }
    __syncthreads();

    const int warp = tid >> 5;
    const int lane = tid & 31;
    const int r0   = base + warp * 2;

    const uint4* prow0 = reinterpret_cast<const uint4*>(pw) + (size_t)r0 * (FAST_K / 8);
    const uint4* prow1 = prow0 + (FAST_K / 8);
    const float4* xe4  = reinterpret_cast<const float4*>(xeven);
    const float4* xo4  = reinterpret_cast<const float4*>(xodd);
    const float* sc0   = scsm + (warp * 2)     * 64;
    const float* sc1   = scsm + (warp * 2 + 1) * 64;

    const unsigned off_bits = 0x64086408u;                  // half2(1032,1032)
    const __half2 off = *reinterpret_cast<const __half2*>(&off_bits);

    float2 acc0 = make_float2(0.f, 0.f);
    float2 acc1 = make_float2(0.f, 0.f);

    #pragma unroll 2
    for (int it = 0; it < 32; ++it) {
        const int c = it * 32 + lane;           // 8-weight chunk, k = 8c..8c+8
        uint4 wa = __ldcs(prow0 + c);
        uint4 wb = __ldcs(prow1 + c);
        float4 xe = xe4[c];                     // {x[8c],x[8c+2],x[8c+4],x[8c+6]}
        float4 xo = xo4[c];                     // {x[8c+1],x[8c+3],x[8c+5],x[8c+7]}

        const float2 xeA = make_float2(xe.x, xe.y);
        const float2 xoA = make_float2(xo.x, xo.y);
        const float2 xeB = make_float2(xe.z, xe.w);
        const float2 xoB = make_float2(xo.z, xo.w);

        // Quant block of this chunk = 2*it + (lane>=16) -> smem broadcast.
        const int col = 2 * it + (lane >> 4);
        const float s0 = sc0[col];
        const float s1 = sc1[col];

        float2 p0 = make_float2(0.f, 0.f);
        p0 = dot4(wa.x, wa.y, xeA, xoA, off, p0);
        p0 = dot4(wa.z, wa.w, xeB, xoB, off, p0);
        acc0 = ffma2(p0, make_float2(s0, s0), acc0);

        float2 p1 = make_float2(0.f, 0.f);
        p1 = dot4(wb.x, wb.y, xeA, xoA, off, p1);
        p1 = dot4(wb.z, wb.w, xeB, xoB, off, p1);
        acc1 = ffma2(p1, make_float2(s1, s1), acc1);
    }

    float a0 = acc0.x + acc0.y;
    float a1 = acc1.x + acc1.y;

    #pragma unroll
    for (int o = 16; o; o >>= 1) {
        a0 += __shfl_xor_sync(0xffffffffu, a0, o);
        a1 += __shfl_xor_sync(0xffffffffu, a1, o);
    }

    if (lane == 0) {
        out[r0]     = a0;
        out[r0 + 1] = a1;
    }
}

// Generic fallback (any K / QB / N), fp32 in/out.
__global__ void q4gemv_generic(const float* __restrict__ x,
                               const int*   __restrict__ pw,
                               const float* __restrict__ scales,
                               float*       __restrict__ out,
                               int N, int K, int QB)
{
    int row = blockIdx.x * blockDim.x + threadIdx.x;
    if (row >= N) return;
    const int halfK = K / 2;
    const int nblk  = K / QB;
    const int ipb   = QB / 2;
    float acc = 0.0f;
    for (int blk = 0; blk < nblk; ++blk) {
        float p = 0.0f;
        for (int i = 0; i < ipb; ++i) {
            int idx = blk * ipb + i;
            unsigned b = (unsigned)pw[(size_t)row * halfK + idx];
            float lo = (float)(int)(b & 15u) - 8.0f;
            float hi = (float)(int)((b >> 4) & 15u) - 8.0f;
            p = fmaf(lo, x[2 * idx],     p);
            p = fmaf(hi, x[2 * idx + 1], p);
        }
        acc = fmaf(p, scales[(size_t)row * nblk + blk], acc);
    }
    out[row] = acc;
}

extern "C" void kernel_launch(void* const* d_in, const int* in_sizes, int n_in,
                              void* d_out, int out_size)
{
    const float* x  = (const float*)d_in[0];
    const int*   pw = (const int*)  d_in[1];
    const float* sc = (const float*)d_in[2];
    float*       out = (float*)d_out;

    const long long K_ll = in_sizes[0];
    const int K  = (int)K_ll;
    const int N  = (int)(((long long)in_sizes[1] * 2) / K_ll);
    const int QB = (int)(((long long)N * K_ll) / in_sizes[2]);

    if (K == FAST_K && QB == 128 && (N % 8) == 0) {
        q4gemv_fast3<<<N / 8, 128>>>(x, pw, sc, out, N);
    } else {
        int threads = 256;
        int blocks = (N + threads - 1) / threads;
        q4gemv_generic<<<blocks, threads>>>(x, pw, sc, out, N, K, QB);
    }
}

// round 13
// speedup vs baseline: 1.5643x; 1.5643x over previous
#include <cuda_runtime.h>
#include <cuda_fp16.h>

// int4-quantized GEMV, QB=128, K=8192. fp16 tensors arrive upcast to fp32.
//   d_in[0] x       : float[8192]
//   d_in[1] packed_w: int32[N, 4096]  (one byte/int32: lo nibble even k,
//                     hi nibble odd k, offset-8)
//   d_in[2] scales  : float[N, 64]
//   d_out  out      : float[N]
//
// R11: MLP-focused. The kernel family is DRAM-latency bound; measured DRAM%
// tracks (bytes in flight per SM)/17KB across R3/R4/R7. This version batches
// 8 LDG.128 per warp (2 rows x unroll 4, loads front-hoisted) and runs 8
// small CTAs/SM (128 thr, 8 rows, grid=1024, <=64 regs) -> 32 warps x 512 B
// = 16 KB/SM in flight. Lean scalar FMA math from R4 (no f32x2 pairs).

#define FAST_K 8192

__global__ void __launch_bounds__(128, 8)
q4gemv_fast4(const float* __restrict__ x,
             const int*   __restrict__ pw,
             const float* __restrict__ scales,
             float*       __restrict__ out,
             int N)
{
    __shared__ __half xs[FAST_K];         // 16 KB, fp16 (lossless re-pack)
    __shared__ float  scsm[8 * 64];       //  2 KB: 8 rows x 64 block scales

    const int tid  = threadIdx.x;
    const int base = blockIdx.x * 8;

    // Stage x: fp32 -> fp16 pairs in SMEM (conflict-free LDS.128 later).
    {
        const float4* xsrc = reinterpret_cast<const float4*>(x);
        uint2*        xdst = reinterpret_cast<uint2*>(xs);
        #pragma unroll
        for (int i = 0; i < (FAST_K / 4) / 128; ++i) {     // 16 iters
            const int idx = tid + i * 128;
            float4 v = xsrc[idx];
            __half2 a = __floats2half2_rn(v.x, v.y);
            __half2 b = __floats2half2_rn(v.z, v.w);
            uint2 u;
            u.x = *reinterpret_cast<unsigned*>(&a);
            u.y = *reinterpret_cast<unsigned*>(&b);
            xdst[idx] = u;
        }
    }
    // Stage this block's 8x64 scales.
    {
        #pragma unroll
        for (int i = 0; i < 4; ++i) {
            const int idx = tid + i * 128;                 // 0..511
            scsm[idx] = scales[(size_t)(base + (idx >> 6)) * 64 + (idx & 63)];
        }
    }
    __syncthreads();

    const int warp = tid >> 5;
    const int lane = tid & 31;
    const int r0   = base + warp * 2;

    const uint4* prow0 = reinterpret_cast<const uint4*>(pw) + (size_t)r0 * (FAST_K / 8);
    const uint4* prow1 = prow0 + (FAST_K / 8);
    const uint4* xsv   = reinterpret_cast<const uint4*>(xs);
    const float* sc0   = scsm + (warp * 2)     * 64;
    const float* sc1   = scsm + (warp * 2 + 1) * 64;

    const unsigned off_bits = 0x64086408u;                 // half2(1032,1032)
    const __half2 off = *reinterpret_cast<const __half2*>(&off_bits);

    float acc0 = 0.0f, acc1 = 0.0f;

    for (int it = 0; it < 8; ++it) {
        // Front-batch 8 independent LDG.128 -> 512 B in flight per warp.
        uint4 wa[4], wb[4];
        #pragma unroll
        for (int j = 0; j < 4; ++j)
            wa[j] = __ldcs(prow0 + it * 128 + j * 32 + lane);
        #pragma unroll
        for (int j = 0; j < 4; ++j)
            wb[j] = __ldcs(prow1 + it * 128 + j * 32 + lane);

        #pragma unroll
        for (int j = 0; j < 4; ++j) {
            const int c = it * 128 + j * 32 + lane;        // 8-weight chunk
            uint4 xv = xsv[c];

            // Quant block = c>>4 = 8*it + 2*j + (lane>=16): smem broadcast.
            const int col = 8 * it + 2 * j + (lane >> 4);
            const float s0 = sc0[col];
            const float s1 = sc1[col];

            float p0 = 0.0f, p1 = 0.0f;
            #pragma unroll
            for (int q = 0; q < 4; ++q) {
                const unsigned b0 = reinterpret_cast<const unsigned*>(&wa[j])[q];
                const unsigned b1 = reinterpret_cast<const unsigned*>(&wb[j])[q];
                float2 xf = __half22float2(
                    reinterpret_cast<const __half2*>(&xv)[q]);

                unsigned t0 = ((b0 | (b0 << 12)) & 0x000F000Fu) | 0x64006400u;
                __half2 h0 = __hsub2(*reinterpret_cast<const __half2*>(&t0), off);
                float2 wf0 = __half22float2(h0);
                p0 = fmaf(wf0.x, xf.x, p0);
                p0 = fmaf(wf0.y, xf.y, p0);

                unsigned t1 = ((b1 | (b1 << 12)) & 0x000F000Fu) | 0x64006400u;
                __half2 h1 = __hsub2(*reinterpret_cast<const __half2*>(&t1), off);
                float2 wf1 = __half22float2(h1);
                p1 = fmaf(wf1.x, xf.x, p1);
                p1 = fmaf(wf1.y, xf.y, p1);
            }
            acc0 = fmaf(p0, s0, acc0);
            acc1 = fmaf(p1, s1, acc1);
        }
    }

    #pragma unroll
    for (int o = 16; o; o >>= 1) {
        acc0 += __shfl_xor_sync(0xffffffffu, acc0, o);
        acc1 += __shfl_xor_sync(0xffffffffu, acc1, o);
    }

    if (lane == 0) {
        out[r0]     = acc0;
        out[r0 + 1] = acc1;
    }
}

// Generic fallback (any K / QB / N), fp32 in/out.
__global__ void q4gemv_generic(const float* __restrict__ x,
                               const int*   __restrict__ pw,
                               const float* __restrict__ scales,
                               float*       __restrict__ out,
                               int N, int K, int QB)
{
    int row = blockIdx.x * blockDim.x + threadIdx.x;
    if (row >= N) return;
    const int halfK = K / 2;
    const int nblk  = K / QB;
    const int ipb   = QB / 2;
    float acc = 0.0f;
    for (int blk = 0; blk < nblk; ++blk) {
        float p = 0.0f;
        for (int i = 0; i < ipb; ++i) {
            int idx = blk * ipb + i;
            unsigned b = (unsigned)pw[(size_t)row * halfK + idx];
            float lo = (float)(int)(b & 15u) - 8.0f;
            float hi = (float)(int)((b >> 4) & 15u) - 8.0f;
            p = fmaf(lo, x[2 * idx],     p);
            p = fmaf(hi, x[2 * idx + 1], p);
        }
        acc = fmaf(p, scales[(size_t)row * nblk + blk], acc);
    }
    out[row] = acc;
}

extern "C" void kernel_launch(void* const* d_in, const int* in_sizes, int n_in,
                              void* d_out, int out_size)
{
    const float* x  = (const float*)d_in[0];
    const int*   pw = (const int*)  d_in[1];
    const float* sc = (const float*)d_in[2];
    float*       out = (float*)d_out;

    const long long K_ll = in_sizes[0];
    const int K  = (int)K_ll;
    const int N  = (int)(((long long)in_sizes[1] * 2) / K_ll);
    const int QB = (int)(((long long)N * K_ll) / in_sizes[2]);

    if (K == FAST_K && QB == 128 && (N % 8) == 0) {
        q4gemv_fast4<<<N / 8, 128>>>(x, pw, sc, out, N);
    } else {
        int threads = 256;
        int blocks = (N + threads - 1) / threads;
        q4gemv_generic<<<blocks, threads>>>(x, pw, sc, out, N, K, QB);
    }
}